// round 1
// baseline (speedup 1.0000x reference)
#include <cuda_runtime.h>
#include <cuda_bf16.h>
#include <cstdint>

// HistogramLoss:
//   hist per (b,c) row of 64 bins over [0,1], normalized; loss = mean |hf - hr|.
//   Both normalizers are exactly HW=262144, so accumulate a single signed
//   histogram: +1 for fake elements, -1 for real elements.
//   loss = sum_bins |signed_count| / (262144 * 6144)

#define ROWS      96          // 32*3
#define BINS      64
#define HW        262144      // 512*512
#define CHUNKS    8           // chunks per row per source
#define CHUNK     (HW / CHUNKS)        // 32768 elements
#define THREADS   256
#define NWARP     (THREADS / 32)
#define PER_TH    (CHUNK / THREADS)    // 128 elements = 32 float4

__device__ int g_hist[ROWS * BINS];    // zero-initialized at module load;
                                       // reduce kernel re-zeroes after reading.

__global__ __launch_bounds__(THREADS)
void hist_kernel(const float* __restrict__ fake, const float* __restrict__ real) {
    __shared__ int sh[NWARP][BINS];

    const int tid  = threadIdx.x;
    const int wid  = tid >> 5;

    // grid = ROWS * 2 * CHUNKS.  [src][row][chunk]
    int id    = blockIdx.x;
    int src   = id >= (ROWS * CHUNKS);
    int r2    = id - src * (ROWS * CHUNKS);
    int row   = r2 >> 3;              // / CHUNKS
    int chunk = r2 & (CHUNKS - 1);

    // zero shared sub-histograms
    for (int i = tid; i < NWARP * BINS; i += THREADS)
        ((int*)sh)[i] = 0;
    __syncthreads();

    const float* base = (src ? real : fake) + (size_t)row * HW + (size_t)chunk * CHUNK;
    const float4* p   = (const float4*)base;

    int* myh = sh[wid];

    #pragma unroll 4
    for (int i = 0; i < PER_TH / 4; i++) {
        float4 v = p[i * THREADS + tid];

        int b0 = (int)(v.x * 64.0f);
        int b1 = (int)(v.y * 64.0f);
        int b2 = (int)(v.z * 64.0f);
        int b3 = (int)(v.w * 64.0f);
        b0 = min(max(b0, 0), 63);
        b1 = min(max(b1, 0), 63);
        b2 = min(max(b2, 0), 63);
        b3 = min(max(b3, 0), 63);

        atomicAdd(&myh[b0], 1);
        atomicAdd(&myh[b1], 1);
        atomicAdd(&myh[b2], 1);
        atomicAdd(&myh[b3], 1);
    }
    __syncthreads();

    // flush: 64 threads, each sums across the NWARP sub-histograms
    if (tid < BINS) {
        int total = 0;
        #pragma unroll
        for (int w = 0; w < NWARP; w++)
            total += sh[w][tid];
        if (src) total = -total;
        atomicAdd(&g_hist[row * BINS + tid], total);
    }
}

__global__ __launch_bounds__(THREADS)
void reduce_kernel(float* __restrict__ out) {
    __shared__ int warp_sums[NWARP];

    const int tid = threadIdx.x;
    int acc = 0;
    for (int i = tid; i < ROWS * BINS; i += THREADS) {
        int h = g_hist[i];
        g_hist[i] = 0;             // self-restore for next graph replay
        acc += (h < 0) ? -h : h;
    }
    // warp reduce
    #pragma unroll
    for (int off = 16; off > 0; off >>= 1)
        acc += __shfl_down_sync(0xFFFFFFFFu, acc, off);
    if ((tid & 31) == 0) warp_sums[tid >> 5] = acc;
    __syncthreads();
    if (tid == 0) {
        int total = 0;
        #pragma unroll
        for (int w = 0; w < NWARP; w++)
            total += warp_sums[w];
        // loss = total / (HW * ROWS*BINS)
        out[0] = (float)total * (1.0f / (262144.0f * 6144.0f));
    }
}

extern "C" void kernel_launch(void* const* d_in, const int* in_sizes, int n_in,
                              void* d_out, int out_size) {
    const float* fake = (const float*)d_in[0];
    const float* real = (const float*)d_in[1];
    float* out = (float*)d_out;

    hist_kernel<<<ROWS * 2 * CHUNKS, THREADS>>>(fake, real);
    reduce_kernel<<<1, THREADS>>>(out);
}